// round 15
// baseline (speedup 1.0000x reference)
#include <cuda_runtime.h>
#include <cuda_bf16.h>
#include <cstdint>

// ---------------------------------------------------------------------------
// miScore: out[i,k] = (1/256) * sum_j sigmoid( y_a[i,:] . (W @ y_b[j,:] + b) )
//
// K1 (grid 384): blocks 0..127  : proj = y_b @ W^T + b (fp32 LDG -> bf16 STS)
//                blocks 128..383: convert y_a -> bf16 (8 f4/thr); zero g_s
// K2: fused HMMA bf16 GEMM (f32 acc) + tanh-sigmoid + atomic row sums
//     CTA 128x128, 256 thr / 8 warps (4M x 2N, warp tile 32x64), BK=64 x 4,
//     3-stage ring, 1 sync per chunk, 2 CTAs/SM = 16 warps/SM.
// K3: broadcast g_s/256 to out (one warp per row)
// ---------------------------------------------------------------------------

#define NUSR 8192
#define HDIM 256

__device__ __align__(16) __nv_bfloat16 g_ya[NUSR * HDIM];     // 4 MB
__device__ __align__(16) __nv_bfloat16 g_projb[NUSR * HDIM];  // 4 MB
__device__ float g_s[NUSR];

// ---------------- cp.async helpers ----------------
__device__ __forceinline__ void cp_async16(uint32_t dst, const void* src) {
    asm volatile("cp.async.cg.shared.global [%0], [%1], 16;" :: "r"(dst), "l"(src));
}
#define CP_COMMIT() asm volatile("cp.async.commit_group;" ::: "memory")
#define CP_WAIT1()  asm volatile("cp.async.wait_group 1;" ::: "memory")
#define CP_WAIT0()  asm volatile("cp.async.wait_group 0;" ::: "memory")

// ---------------- mma / ldmatrix ----------------
__device__ __forceinline__ void ldsm_x4(uint32_t* r, uint32_t addr) {
    asm volatile("ldmatrix.sync.aligned.m8n8.x4.shared.b16 {%0,%1,%2,%3}, [%4];"
                 : "=r"(r[0]), "=r"(r[1]), "=r"(r[2]), "=r"(r[3]) : "r"(addr));
}
__device__ __forceinline__ void mma16816(float* c, const uint32_t* a, const uint32_t* b) {
    asm volatile(
        "mma.sync.aligned.m16n8k16.row.col.f32.bf16.bf16.f32 "
        "{%0,%1,%2,%3}, {%4,%5,%6,%7}, {%8,%9}, {%0,%1,%2,%3};"
        : "+f"(c[0]), "+f"(c[1]), "+f"(c[2]), "+f"(c[3])
        : "r"(a[0]), "r"(a[1]), "r"(a[2]), "r"(a[3]), "r"(b[0]), "r"(b[1]));
}
__device__ __forceinline__ float fast_tanh(float x) {
    float t;
    asm("tanh.approx.f32 %0, %1;" : "=f"(t) : "f"(x));
    return t;
}
__device__ __forceinline__ uint32_t bf2x2(float a, float b) {
    __nv_bfloat162 h = __floats2bfloat162_rn(a, b);
    return *(uint32_t*)&h;
}

// ===========================================================================
// K1: proj (fp32 sources, blocks 0..127) || y_a convert (blocks 128..383).
// ===========================================================================
#define PSROW 40
#define PA_BYTES (128 * PSROW * 2)

__global__ void __launch_bounds__(256, 1) proj_and_convert_kernel(
        const float* __restrict__ bias, const float* __restrict__ ya,
        const float* __restrict__ yb, const float* __restrict__ W) {
    __shared__ __align__(16) char smem[2 * PA_BYTES];

    const int tid = threadIdx.x;
    const int bx = blockIdx.x;

    if (bx >= 128) {   // ---- y_a conversion (256 blocks x 8 f4/thr) ----
        const int base = (bx - 128) * 2048;
        __nv_bfloat162* dst = (__nv_bfloat162*)g_ya;
        #pragma unroll
        for (int u = 0; u < 8; u++) {
            const int off = base + u * 256 + tid;
            float4 v = ((const float4*)ya)[off];
            dst[off * 2 + 0] = __floats2bfloat162_rn(v.x, v.y);
            dst[off * 2 + 1] = __floats2bfloat162_rn(v.z, v.w);
        }
        if (tid < 8) {
            const int o = (bx - 128) * 32 + tid * 4;
            *(float4*)&g_s[o] = make_float4(0.f, 0.f, 0.f, 0.f);
        }
        return;
    }

    // ---- proj: CTA 128(Mj) x 128(Ns), K=256 as 8 BK=32 chunks ----
    const uint32_t sbase = (uint32_t)__cvta_generic_to_shared(smem);
    const int wid = tid >> 5, lane = tid & 31;
    const int wm0 = (wid & 1) * 64;
    const int wn0 = (wid >> 1) * 32;
    const int j0 = (bx >> 1) * 128;
    const int s0 = (bx & 1) * 128;

    const int r0g = tid >> 2,          c0g = tid & 3;
    const int r1g = (tid + 256) >> 2,  c1g = (tid + 256) & 3;

    float acc[4][4][4];
    #pragma unroll
    for (int mt = 0; mt < 4; mt++)
        #pragma unroll
        for (int nt = 0; nt < 4; nt++)
            #pragma unroll
            for (int e = 0; e < 4; e++) acc[mt][nt][e] = 0.0f;

    float4 rA[2][2], rB[2][2];
    auto ldg_chunk = [&](int kt, float4 (*A)[2], float4 (*B)[2]) {
        const float* a0 = yb + (size_t)(j0 + r0g) * HDIM + kt + c0g * 8;
        const float* a1 = yb + (size_t)(j0 + r1g) * HDIM + kt + c1g * 8;
        const float* b0 = W  + (size_t)(s0 + r0g) * HDIM + kt + c0g * 8;
        const float* b1 = W  + (size_t)(s0 + r1g) * HDIM + kt + c1g * 8;
        A[0][0] = *(const float4*)a0; A[0][1] = *(const float4*)(a0 + 4);
        A[1][0] = *(const float4*)a1; A[1][1] = *(const float4*)(a1 + 4);
        B[0][0] = *(const float4*)b0; B[0][1] = *(const float4*)(b0 + 4);
        B[1][0] = *(const float4*)b1; B[1][1] = *(const float4*)(b1 + 4);
    };
    auto sts_chunk = [&](float4 (*A)[2], float4 (*B)[2]) {
        #pragma unroll
        for (int t = 0; t < 2; t++) {
            const int row = t == 0 ? r0g : r1g;
            const int c16 = t == 0 ? c0g : c1g;
            const uint32_t off = (row * PSROW + c16 * 8) * 2;
            uint4 va, vb;
            va.x = bf2x2(A[t][0].x, A[t][0].y); va.y = bf2x2(A[t][0].z, A[t][0].w);
            va.z = bf2x2(A[t][1].x, A[t][1].y); va.w = bf2x2(A[t][1].z, A[t][1].w);
            vb.x = bf2x2(B[t][0].x, B[t][0].y); vb.y = bf2x2(B[t][0].z, B[t][0].w);
            vb.z = bf2x2(B[t][1].x, B[t][1].y); vb.w = bf2x2(B[t][1].z, B[t][1].w);
            asm volatile("st.shared.v4.b32 [%0], {%1,%2,%3,%4};"
                         :: "r"(sbase + off), "r"(va.x), "r"(va.y), "r"(va.z), "r"(va.w));
            asm volatile("st.shared.v4.b32 [%0], {%1,%2,%3,%4};"
                         :: "r"(sbase + PA_BYTES + off),
                            "r"(vb.x), "r"(vb.y), "r"(vb.z), "r"(vb.w));
        }
    };

    ldg_chunk(0, rA, rB);

    const int sub = lane >> 3, r8 = lane & 7;

    float4 nA[2][2], nB[2][2];
    #pragma unroll 1
    for (int it = 0; it < 8; it++) {
        __syncthreads();
        sts_chunk(rA, rB);
        if (it < 7) ldg_chunk((it + 1) * 32, nA, nB);
        __syncthreads();

        #pragma unroll
        for (int kk = 0; kk < 32; kk += 16) {
            uint32_t afrag[4][4];
            #pragma unroll
            for (int mt = 0; mt < 4; mt++) {
                int row = wm0 + mt * 16 + (sub & 1) * 8 + r8;
                int col = kk + (sub >> 1) * 8;
                ldsm_x4(afrag[mt], sbase + (row * PSROW + col) * 2);
            }
            uint32_t bfrag[4][2];
            #pragma unroll
            for (int p = 0; p < 2; p++) {
                int row = wn0 + p * 16 + (sub >> 1) * 8 + r8;
                int col = kk + (sub & 1) * 8;
                uint32_t t4[4];
                ldsm_x4(t4, sbase + PA_BYTES + (row * PSROW + col) * 2);
                bfrag[p * 2 + 0][0] = t4[0]; bfrag[p * 2 + 0][1] = t4[1];
                bfrag[p * 2 + 1][0] = t4[2]; bfrag[p * 2 + 1][1] = t4[3];
            }
            #pragma unroll
            for (int mt = 0; mt < 4; mt++)
                #pragma unroll
                for (int nt = 0; nt < 4; nt++)
                    mma16816(acc[mt][nt], afrag[mt], bfrag[nt]);
        }
        #pragma unroll
        for (int t = 0; t < 2; t++) {
            rA[t][0] = nA[t][0]; rA[t][1] = nA[t][1];
            rB[t][0] = nB[t][0]; rB[t][1] = nB[t][1];
        }
    }

    #pragma unroll
    for (int nt = 0; nt < 4; nt++) {
        const int gc = s0 + wn0 + nt * 8 + 2 * (lane & 3);
        const float b0 = bias[gc], b1 = bias[gc + 1];
        #pragma unroll
        for (int mt = 0; mt < 4; mt++) {
            const int rlo = j0 + wm0 + mt * 16 + (lane >> 2);
            *((__nv_bfloat162*)&g_projb[(size_t)rlo * HDIM + gc]) =
                __floats2bfloat162_rn(acc[mt][nt][0] + b0, acc[mt][nt][1] + b1);
            *((__nv_bfloat162*)&g_projb[(size_t)(rlo + 8) * HDIM + gc]) =
                __floats2bfloat162_rn(acc[mt][nt][2] + b0, acc[mt][nt][3] + b1);
        }
    }
}

// ===========================================================================
// K2: fused HMMA bf16 GEMM (f32 acc) + sigmoid + atomic row sums.
//   CTA 128(M=i) x 128(N=j), 256 threads, 8 warps as 4(M) x 2(N),
//   warp tile 32x64 -> acc[2][8][4] = 64 regs. 2 CTAs/SM = 16 warps/SM.
//   K=256 as 4 BK=64 chunks, 3-stage ring, ONE sync per chunk.
// ===========================================================================
#define SROWB 144
#define STG_A (128 * SROWB)                         // 18432
#define STG_BYTES (2 * STG_A)                       // 36864
#define NST 3
#define FUSED_SMEM (NST * STG_BYTES)                // 110592

__global__ void __launch_bounds__(256, 2) fused_hmma_kernel() {
    extern __shared__ __align__(16) char smem[];
    const uint32_t sbase = (uint32_t)__cvta_generic_to_shared(smem);

    const int tid = threadIdx.x;
    const int wid = tid >> 5, lane = tid & 31;
    const int wm0 = (wid & 3) * 32;                 // 4 M-warps
    const int wn0 = (wid >> 2) * 64;                // 2 N-warps
    const int sub = lane >> 3, r8 = lane & 7;
    const int i0 = blockIdx.y * 128;
    const int j0 = blockIdx.x * 128;

    float acc[2][8][4];
    #pragma unroll
    for (int mt = 0; mt < 2; mt++)
        #pragma unroll
        for (int nt = 0; nt < 8; nt++)
            #pragma unroll
            for (int e = 0; e < 4; e++) acc[mt][nt][e] = 0.0f;

    auto load_chunk = [&](int g) {
        const uint32_t dstb = sbase + (g % NST) * STG_BYTES;
        const int kt = g * 64;
        #pragma unroll
        for (int t = 0; t < 8; t++) {
            int gg = tid + t * 256;
            if (gg < 1024) {
                int row = gg >> 3, c = gg & 7;
                cp_async16(dstb + row * SROWB + c * 16,
                           g_ya + (size_t)(i0 + row) * HDIM + kt + c * 8);
            } else {
                int gb = gg - 1024;
                int row = gb >> 3, c = gb & 7;
                cp_async16(dstb + STG_A + row * SROWB + c * 16,
                           g_projb + (size_t)(j0 + row) * HDIM + kt + c * 8);
            }
        }
        CP_COMMIT();
    };

    load_chunk(0);

    #pragma unroll 1
    for (int g = 0; g < 4; g++) {
        if (g < 3) { load_chunk(g + 1); CP_WAIT1(); }
        else       { CP_WAIT0(); }
        __syncthreads();

        const uint32_t aBase = sbase + (g % NST) * STG_BYTES;
        const uint32_t bBase = aBase + STG_A;

        #pragma unroll
        for (int kk = 0; kk < 64; kk += 16) {
            uint32_t afrag[2][4];
            #pragma unroll
            for (int mt = 0; mt < 2; mt++) {
                int row = wm0 + mt * 16 + (sub & 1) * 8 + r8;
                int col = kk + (sub >> 1) * 8;
                ldsm_x4(afrag[mt], aBase + row * SROWB + col * 2);
            }
            uint32_t bfrag[8][2];
            #pragma unroll
            for (int p = 0; p < 4; p++) {
                int row = wn0 + p * 16 + (sub >> 1) * 8 + r8;
                int col = kk + (sub & 1) * 8;
                uint32_t t4[4];
                ldsm_x4(t4, bBase + row * SROWB + col * 2);
                bfrag[p * 2 + 0][0] = t4[0]; bfrag[p * 2 + 0][1] = t4[1];
                bfrag[p * 2 + 1][0] = t4[2]; bfrag[p * 2 + 1][1] = t4[3];
            }
            #pragma unroll
            for (int mt = 0; mt < 2; mt++)
                #pragma unroll
                for (int nt = 0; nt < 8; nt++)
                    mma16816(acc[mt][nt], afrag[mt], bfrag[nt]);
        }
    }

    // ---- epilogue: sigmoid(x) = 0.5*tanh(x/2) + 0.5 ; atomic row sums ----
    float rs[2][2];
    #pragma unroll
    for (int mt = 0; mt < 2; mt++) { rs[mt][0] = 0.0f; rs[mt][1] = 0.0f; }
    #pragma unroll
    for (int mt = 0; mt < 2; mt++)
        #pragma unroll
        for (int nt = 0; nt < 8; nt++) {
            rs[mt][0] += 0.5f * fast_tanh(0.5f * acc[mt][nt][0])
                       + 0.5f * fast_tanh(0.5f * acc[mt][nt][1]);
            rs[mt][1] += 0.5f * fast_tanh(0.5f * acc[mt][nt][2])
                       + 0.5f * fast_tanh(0.5f * acc[mt][nt][3]);
        }
    #pragma unroll
    for (int mt = 0; mt < 2; mt++)
        #pragma unroll
        for (int h = 0; h < 2; h++) {
            rs[mt][h] += __shfl_xor_sync(0xffffffffu, rs[mt][h], 1);
            rs[mt][h] += __shfl_xor_sync(0xffffffffu, rs[mt][h], 2);
        }
    if ((lane & 3) == 0) {
        const int rq = lane >> 2;
        #pragma unroll
        for (int mt = 0; mt < 2; mt++) {
            atomicAdd(&g_s[i0 + wm0 + mt * 16 + 0 + rq], rs[mt][0] + 32.0f);
            atomicAdd(&g_s[i0 + wm0 + mt * 16 + 8 + rq], rs[mt][1] + 32.0f);
        }
    }
}

// ===========================================================================
// K3: broadcast g_s/256 to out. 2048 blocks x 128 thr; one warp per row.
// ===========================================================================
__global__ void bcast_kernel(float* __restrict__ out) {
    const int wid = threadIdx.x >> 5, lane = threadIdx.x & 31;
    const int row = blockIdx.x * 4 + wid;
    const float v = g_s[row] * (1.0f / 256.0f);
    float4* dst = (float4*)(out + (size_t)row * HDIM);
    const float4 vv = make_float4(v, v, v, v);
    dst[lane]      = vv;
    dst[lane + 32] = vv;
}

// ===========================================================================
extern "C" void kernel_launch(void* const* d_in, const int* in_sizes, int n_in,
                              void* d_out, int out_size) {
    const float* y_a = (const float*)d_in[0];
    const float* y_b = (const float*)d_in[1];
    const float* W   = (const float*)d_in[2];
    const float* b   = (const float*)d_in[3];
    float* out = (float*)d_out;

    cudaFuncSetAttribute(fused_hmma_kernel,
                         cudaFuncAttributeMaxDynamicSharedMemorySize, FUSED_SMEM);

    proj_and_convert_kernel<<<384, 256>>>(b, y_a, y_b, W);
    fused_hmma_kernel<<<dim3(64, 64), 256, FUSED_SMEM>>>();
    bcast_kernel<<<NUSR / 4, 128>>>(out);
}